// round 9
// baseline (speedup 1.0000x reference)
#include <cuda_runtime.h>

#define T_  256
#define B_  1024
#define NX_ 256
#define NY_ 64
#define NU_ 64
#define ND_ 32
#define TB_ (T_*B_)

typedef unsigned long long ull;

// ---- device globals ----
__device__ float  g_WxT [NX_*NX_];   // [k][j]
__device__ float  g_WudT[96*NX_];    // [k][j]
__device__ float  g_WyT [NX_*NY_];   // [k][j]
__device__ double g_acc[6];          // 0:sxmin 1:sxmax 2:sumin 3:sumax 4:sdx 5:dxd

// ---- packed fp32x2 helpers ----
__device__ __forceinline__ ull pk2(float lo, float hi){
    ull r;
    asm("mov.b64 %0, {%1, %2};" : "=l"(r) : "f"(lo), "f"(hi));
    return r;
}
__device__ __forceinline__ void upk2(ull v, float& lo, float& hi){
    asm("mov.b64 {%0, %1}, %2;" : "=f"(lo), "=f"(hi) : "l"(v));
}
__device__ __forceinline__ ull fma2(ull a, ull b, ull c){
    ull d;
    asm("fma.rn.f32x2 %0, %1, %2, %3;" : "=l"(d) : "l"(a), "l"(b), "l"(c));
    return d;
}
__device__ __forceinline__ float warp_sum(float v){
    #pragma unroll
    for (int o = 16; o > 0; o >>= 1) v += __shfl_down_sync(0xffffffffu, v, o);
    return v;
}

// ============================================================================
// K0
// ============================================================================
__global__ void k0_prep(const float* __restrict__ Wx, const float* __restrict__ Wu,
                        const float* __restrict__ Wd, const float* __restrict__ Wy){
    int tid = blockIdx.x * blockDim.x + threadIdx.x;
    int nt  = gridDim.x * blockDim.x;
    if (blockIdx.x == 0 && threadIdx.x < 6) g_acc[threadIdx.x] = 0.0;
    for (int i = tid; i < NX_*NX_; i += nt){ int j = i / NX_, k = i % NX_; g_WxT[k*NX_ + j] = Wx[i]; }
    for (int i = tid; i < NX_*NU_; i += nt){ int j = i / NU_, k = i % NU_; g_WudT[k*NX_ + j] = Wu[i]; }
    for (int i = tid; i < NX_*ND_; i += nt){ int j = i / ND_, k = i % ND_; g_WudT[(64 + k)*NX_ + j] = Wd[i]; }
    for (int i = tid; i < NY_*NX_; i += nt){ int j = i / NX_, k = i % NX_; g_WyT[k*NY_ + j] = Wy[i]; }
}

// ============================================================================
// K1: S = fu + fd + bx. CTA = 128 rows x 64 cols, thread = 8r x 4c.
//     Weights staged in smem (24KB) to remove in-loop LDG latency.
// ============================================================================
__global__ __launch_bounds__(256, 2) void k1_fud(const float* __restrict__ U,
                                                 const float* __restrict__ D,
                                                 const float* __restrict__ bx,
                                                 const float* __restrict__ bu,
                                                 const float* __restrict__ bd,
                                                 float* __restrict__ Xout){
    __shared__ __align__(16) float uds[96*132];
    __shared__ __align__(16) float ws[96*64];
    __shared__ float red[24];

    const int tid = threadIdx.x;
    const long g0 = (long)blockIdx.x * 128;
    const int cb  = blockIdx.y * 64;

    for (int idx = tid; idx < 96*64; idx += 256){
        int k = idx >> 6, c = idx & 63;
        ws[idx] = g_WudT[k*NX_ + cb + c];
    }
    for (int idx = tid; idx < 128*64; idx += 256){
        int r = idx >> 6, k = idx & 63;
        uds[k*132 + r] = U[(g0 + r)*NU_ + k];
    }
    for (int idx = tid; idx < 128*32; idx += 256){
        int r = idx >> 5, k = idx & 31;
        uds[(64 + k)*132 + r] = D[(g0 + r)*ND_ + k];
    }
    __syncthreads();

    const int r0 = (tid >> 4) * 8;
    const int cl = (tid & 15) * 4;        // local col in [0,64)
    const int c0 = cb + cl;

    ull accu[16], accd[16];
    #pragma unroll
    for (int i = 0; i < 16; i++){ accu[i] = 0ull; accd[i] = 0ull; }

    #pragma unroll 4
    for (int k = 0; k < 64; k++){
        float4 w = *(const float4*)&ws[k*64 + cl];
        ull w2[4] = { pk2(w.x, w.x), pk2(w.y, w.y), pk2(w.z, w.z), pk2(w.w, w.w) };
        ulonglong2 qa = *(const ulonglong2*)&uds[k*132 + r0];
        ulonglong2 qb = *(const ulonglong2*)&uds[k*132 + r0 + 4];
        #pragma unroll
        for (int c = 0; c < 4; c++){
            accu[c*4 + 0] = fma2(qa.x, w2[c], accu[c*4 + 0]);
            accu[c*4 + 1] = fma2(qa.y, w2[c], accu[c*4 + 1]);
            accu[c*4 + 2] = fma2(qb.x, w2[c], accu[c*4 + 2]);
            accu[c*4 + 3] = fma2(qb.y, w2[c], accu[c*4 + 3]);
        }
    }
    #pragma unroll 4
    for (int k = 64; k < 96; k++){
        float4 w = *(const float4*)&ws[k*64 + cl];
        ull w2[4] = { pk2(w.x, w.x), pk2(w.y, w.y), pk2(w.z, w.z), pk2(w.w, w.w) };
        ulonglong2 qa = *(const ulonglong2*)&uds[k*132 + r0];
        ulonglong2 qb = *(const ulonglong2*)&uds[k*132 + r0 + 4];
        #pragma unroll
        for (int c = 0; c < 4; c++){
            accd[c*4 + 0] = fma2(qa.x, w2[c], accd[c*4 + 0]);
            accd[c*4 + 1] = fma2(qa.y, w2[c], accd[c*4 + 1]);
            accd[c*4 + 2] = fma2(qb.x, w2[c], accd[c*4 + 2]);
            accd[c*4 + 3] = fma2(qb.y, w2[c], accd[c*4 + 3]);
        }
    }

    float s0 = 0.f, s1 = 0.f, s2 = 0.f;
    float vout[8][4];
    #pragma unroll
    for (int c = 0; c < 4; c++){
        float buc = bu[c0 + c], bdc = bd[c0 + c], bxc = bx[c0 + c];
        #pragma unroll
        for (int p = 0; p < 4; p++){
            float fu0, fu1, fd0, fd1;
            upk2(accu[c*4 + p], fu0, fu1);
            upk2(accd[c*4 + p], fd0, fd1);
            fu0 += buc; fu1 += buc; fd0 += bdc; fd1 += bdc;
            s0 += fmaxf(-fu0 - 1.f, 0.f) + fmaxf(-fu1 - 1.f, 0.f);
            s1 += fmaxf( fu0 - 1.f, 0.f) + fmaxf( fu1 - 1.f, 0.f);
            s2 += fmaxf(-fd0 - 1.f, 0.f) + fmaxf(fd0 - 1.f, 0.f)
                + fmaxf(-fd1 - 1.f, 0.f) + fmaxf(fd1 - 1.f, 0.f);
            vout[2*p    ][c] = fu0 + fd0 + bxc;
            vout[2*p + 1][c] = fu1 + fd1 + bxc;
        }
    }
    #pragma unroll
    for (int rr = 0; rr < 8; rr++){
        float4 o = make_float4(vout[rr][0], vout[rr][1], vout[rr][2], vout[rr][3]);
        *(float4*)&Xout[(g0 + r0 + rr)*NX_ + c0] = o;
    }

    s0 = warp_sum(s0); s1 = warp_sum(s1); s2 = warp_sum(s2);
    int lane = tid & 31, w = tid >> 5;
    if (lane == 0){ red[w] = s0; red[8 + w] = s1; red[16 + w] = s2; }
    __syncthreads();
    if (tid == 0){
        float a = 0, b = 0, c = 0;
        #pragma unroll
        for (int i = 0; i < 8; i++){ a += red[i]; b += red[8 + i]; c += red[16 + i]; }
        atomicAdd(&g_acc[2], (double)a);
        atomicAdd(&g_acc[3], (double)b);
        atomicAdd(&g_acc[5], (double)c);
    }
}

// ============================================================================
// K2: recurrence. 128 CTAs x 8 rows, 512 threads = 256 cols x 2 k-halves
//     (4 warps/SMSP for latency hiding). Thread = 1 col x 8 rows.
//     192KB of Wx cached in smem as float4-per-4k blocks (wc4[half][kb][j]);
//     rows [96,128) of each half streamed with 2x batch-16 prefetch.
// ============================================================================
// floats: wc4 2*24*256*4 = 49152 | xcT 2048 | ps 2*256*8 = 4096 | red 48
#define K2_SMEM_FLOATS (49152 + 2048 + 4096 + 48)
#define K2_SMEM_BYTES  (K2_SMEM_FLOATS * 4)

__global__ __launch_bounds__(512, 1) void k2_rec(const float* __restrict__ x0,
                                                 float* __restrict__ Xout){
    extern __shared__ __align__(16) float sm[];
    float* wc  = sm;                         // [half][kb<24][j<256] float4
    float* xcT = sm + 49152;                 // [k][m] 256*8
    float* ps  = sm + 49152 + 2048;          // [half][j][m] 2*256*8
    float* red = sm + 49152 + 2048 + 4096;   // 48

    const int tid = threadIdx.x;
    const int kh  = tid >> 8;                // k-half (also epilogue row-half)
    const int j   = tid & 255;               // own column
    const long rb = (long)blockIdx.x * 8;

    // fill wc4: half h, block kb, col j -> w rows h*128 + kb*4 + [0,4)
    for (int idx = tid; idx < 2*24*256; idx += 512){
        int h  = idx / (24*256);
        int rm = idx % (24*256);
        int kb = rm >> 8;
        int jj = rm & 255;
        float4 v;
        v.x = g_WxT[(h*128 + kb*4 + 0)*NX_ + jj];
        v.y = g_WxT[(h*128 + kb*4 + 1)*NX_ + jj];
        v.z = g_WxT[(h*128 + kb*4 + 2)*NX_ + jj];
        v.w = g_WxT[(h*128 + kb*4 + 3)*NX_ + jj];
        *(float4*)&wc[idx*4] = v;
    }
    for (int idx = tid; idx < 8*NX_; idx += 512){
        int m = idx >> 8, k = idx & 255;
        xcT[k*8 + m] = x0[(rb + m)*NX_ + k];
    }
    __syncthreads();

    float sxmin = 0.f, sxmax = 0.f, sdx = 0.f;

    const float4* wc4b  = ((const float4*)wc) + kh*24*256 + j;  // + kb*256
    const float*  wgbase = g_WxT + (kh*128 + 96)*NX_ + j;
    const float*  xb     = xcT + (kh*128)*8;
    float*        psme   = ps + (kh*256 + j)*8;

    for (int t = 0; t < T_; t++){
        float* Srow = Xout + ((long)t*B_ + rb)*NX_;

        // epilogue inputs (own col j, rows kh*4..kh*4+3) - issued early
        float sv0 = Srow[(kh*4 + 0)*NX_ + j];
        float sv1 = Srow[(kh*4 + 1)*NX_ + j];
        float sv2 = Srow[(kh*4 + 2)*NX_ + j];
        float sv3 = Srow[(kh*4 + 3)*NX_ + j];

        ull a[4] = {0,0,0,0};
        float wg[16];

        // P0: prefetch global rows [96,112)
        #pragma unroll
        for (int i = 0; i < 16; i++) wg[i] = wgbase[i*NX_];

        // cached k [0,48)
        #pragma unroll 4
        for (int kb = 0; kb < 12; kb++){
            float4 w4 = wc4b[kb*256];
            #pragma unroll
            for (int e = 0; e < 4; e++){
                float we = (e == 0) ? w4.x : (e == 1) ? w4.y : (e == 2) ? w4.z : w4.w;
                ull w2 = pk2(we, we);
                const ulonglong2* xr = (const ulonglong2*)(xb + (kb*4 + e)*8);
                ulonglong2 q01 = xr[0], q23 = xr[1];
                a[0] = fma2(q01.x, w2, a[0]); a[1] = fma2(q01.y, w2, a[1]);
                a[2] = fma2(q23.x, w2, a[2]); a[3] = fma2(q23.y, w2, a[3]);
            }
        }
        // C0: consume global k [96,112)
        #pragma unroll
        for (int i = 0; i < 16; i++){
            ull w2 = pk2(wg[i], wg[i]);
            const ulonglong2* xr = (const ulonglong2*)(xb + (96 + i)*8);
            ulonglong2 q01 = xr[0], q23 = xr[1];
            a[0] = fma2(q01.x, w2, a[0]); a[1] = fma2(q01.y, w2, a[1]);
            a[2] = fma2(q23.x, w2, a[2]); a[3] = fma2(q23.y, w2, a[3]);
        }
        // P1: prefetch global rows [112,128)
        #pragma unroll
        for (int i = 0; i < 16; i++) wg[i] = wgbase[(16 + i)*NX_];

        // cached k [48,96)
        #pragma unroll 4
        for (int kb = 12; kb < 24; kb++){
            float4 w4 = wc4b[kb*256];
            #pragma unroll
            for (int e = 0; e < 4; e++){
                float we = (e == 0) ? w4.x : (e == 1) ? w4.y : (e == 2) ? w4.z : w4.w;
                ull w2 = pk2(we, we);
                const ulonglong2* xr = (const ulonglong2*)(xb + (kb*4 + e)*8);
                ulonglong2 q01 = xr[0], q23 = xr[1];
                a[0] = fma2(q01.x, w2, a[0]); a[1] = fma2(q01.y, w2, a[1]);
                a[2] = fma2(q23.x, w2, a[2]); a[3] = fma2(q23.y, w2, a[3]);
            }
        }
        // C1: consume global k [112,128)
        #pragma unroll
        for (int i = 0; i < 16; i++){
            ull w2 = pk2(wg[i], wg[i]);
            const ulonglong2* xr = (const ulonglong2*)(xb + (112 + i)*8);
            ulonglong2 q01 = xr[0], q23 = xr[1];
            a[0] = fma2(q01.x, w2, a[0]); a[1] = fma2(q01.y, w2, a[1]);
            a[2] = fma2(q23.x, w2, a[2]); a[3] = fma2(q23.y, w2, a[3]);
        }

        // store partials: ps[kh][j][0..7]
        {
            float f0, f1, f2, f3, f4, f5, f6, f7;
            upk2(a[0], f0, f1); upk2(a[1], f2, f3);
            upk2(a[2], f4, f5); upk2(a[3], f6, f7);
            *(float4*)&psme[0] = make_float4(f0, f1, f2, f3);
            *(float4*)&psme[4] = make_float4(f4, f5, f6, f7);
        }
        __syncthreads();

        // epilogue: thread owns col j, rows kh*4..kh*4+3
        {
            const int m0 = kh*4;
            float4 p0 = *(const float4*)&ps[(0*256 + j)*8 + m0];
            float4 p1 = *(const float4*)&ps[(1*256 + j)*8 + m0];
            float4 xo = *(const float4*)&xcT[j*8 + m0];
            float v0 = p0.x + p1.x + sv0;
            float v1 = p0.y + p1.y + sv1;
            float v2 = p0.z + p1.z + sv2;
            float v3 = p0.w + p1.w + sv3;
            sxmin += fmaxf(-v0-1.f,0.f) + fmaxf(-v1-1.f,0.f) + fmaxf(-v2-1.f,0.f) + fmaxf(-v3-1.f,0.f);
            sxmax += fmaxf( v0-1.f,0.f) + fmaxf( v1-1.f,0.f) + fmaxf( v2-1.f,0.f) + fmaxf( v3-1.f,0.f);
            float d0 = v0-xo.x, d1 = v1-xo.y, d2 = v2-xo.z, d3 = v3-xo.w;
            sdx += d0*d0 + d1*d1 + d2*d2 + d3*d3;
            Srow[(m0+0)*NX_ + j] = v0;
            Srow[(m0+1)*NX_ + j] = v1;
            Srow[(m0+2)*NX_ + j] = v2;
            Srow[(m0+3)*NX_ + j] = v3;
            *(float4*)&xcT[j*8 + m0] = make_float4(v0, v1, v2, v3);
        }
        __syncthreads();
    }

    sxmin = warp_sum(sxmin); sxmax = warp_sum(sxmax); sdx = warp_sum(sdx);
    int lane = tid & 31, w = tid >> 5;
    if (lane == 0){ red[w] = sxmin; red[16 + w] = sxmax; red[32 + w] = sdx; }
    __syncthreads();
    if (tid == 0){
        float a = 0, b = 0, c = 0;
        #pragma unroll
        for (int i = 0; i < 16; i++){ a += red[i]; b += red[16 + i]; c += red[32 + i]; }
        atomicAdd(&g_acc[0], (double)a);
        atomicAdd(&g_acc[1], (double)b);
        atomicAdd(&g_acc[4], (double)c);
    }
}

// ============================================================================
// K3: Y = X @ Wy^T + by. CTA = 128 rows x 64 cols, thread = 8r x 4c,
//     K staged in 4 chunks of 64; weights ALSO staged in smem per chunk.
// ============================================================================
__global__ __launch_bounds__(256, 4) void k3_y(const float* __restrict__ Xout,
                                               const float* __restrict__ by,
                                               float* __restrict__ Yout){
    __shared__ __align__(16) float xs[64*132];
    __shared__ __align__(16) float ws[64*64];
    const int tid = threadIdx.x;
    const long g0 = (long)blockIdx.x * 128;
    const int r0 = (tid >> 4) * 8;
    const int c0 = (tid & 15) * 4;

    ull acc[16];
    #pragma unroll
    for (int i = 0; i < 16; i++) acc[i] = 0ull;

    for (int ch = 0; ch < 4; ch++){
        if (ch) __syncthreads();
        for (int idx = tid; idx < 128*64; idx += 256){
            int r = idx >> 6, k = idx & 63;
            xs[k*132 + r] = Xout[(g0 + r)*NX_ + ch*64 + k];
        }
        for (int idx = tid; idx < 64*64; idx += 256){
            int k = idx >> 6, c = idx & 63;
            ws[idx] = g_WyT[(ch*64 + k)*NY_ + c];
        }
        __syncthreads();

        #pragma unroll 4
        for (int k = 0; k < 64; k++){
            float4 w = *(const float4*)&ws[k*64 + c0];
            ull w2[4] = { pk2(w.x, w.x), pk2(w.y, w.y), pk2(w.z, w.z), pk2(w.w, w.w) };
            ulonglong2 qa = *(const ulonglong2*)&xs[k*132 + r0];
            ulonglong2 qb = *(const ulonglong2*)&xs[k*132 + r0 + 4];
            #pragma unroll
            for (int c = 0; c < 4; c++){
                acc[c*4 + 0] = fma2(qa.x, w2[c], acc[c*4 + 0]);
                acc[c*4 + 1] = fma2(qa.y, w2[c], acc[c*4 + 1]);
                acc[c*4 + 2] = fma2(qb.x, w2[c], acc[c*4 + 2]);
                acc[c*4 + 3] = fma2(qb.y, w2[c], acc[c*4 + 3]);
            }
        }
    }

    float byv[4] = { by[c0], by[c0+1], by[c0+2], by[c0+3] };
    float vout[8][4];
    #pragma unroll
    for (int c = 0; c < 4; c++){
        #pragma unroll
        for (int p = 0; p < 4; p++){
            float lo, hi;
            upk2(acc[c*4 + p], lo, hi);
            vout[2*p    ][c] = lo + byv[c];
            vout[2*p + 1][c] = hi + byv[c];
        }
    }
    #pragma unroll
    for (int rr = 0; rr < 8; rr++){
        float4 o = make_float4(vout[rr][0], vout[rr][1], vout[rr][2], vout[rr][3]);
        *(float4*)&Yout[(g0 + r0 + rr)*NY_ + c0] = o;
    }
}

// ============================================================================
// K4
// ============================================================================
__global__ void k4_fin(float* __restrict__ out_reg){
    double inv = 1.0 / ((double)T_ * (double)B_ * (double)NX_);
    double s = g_acc[0] + g_acc[1] + 2.0*(g_acc[2] + g_acc[3]) + g_acc[4] + g_acc[5];
    *out_reg = (float)(0.2 * s * inv);
}

extern "C" void kernel_launch(void* const* d_in, const int* in_sizes, int n_in,
                              void* d_out, int out_size){
    const float* x  = (const float*)d_in[0];
    const float* U  = (const float*)d_in[1];
    const float* D  = (const float*)d_in[2];
    const float* Wx = (const float*)d_in[3];
    const float* bx = (const float*)d_in[4];
    const float* Wu = (const float*)d_in[5];
    const float* bu = (const float*)d_in[6];
    const float* Wd = (const float*)d_in[7];
    const float* bd = (const float*)d_in[8];
    const float* Wy = (const float*)d_in[9];
    const float* by = (const float*)d_in[10];

    float* out  = (float*)d_out;
    float* Xout = out;
    float* Yout = out + (size_t)TB_ * NX_;
    float* Rout = out + (size_t)TB_ * NX_ + (size_t)TB_ * NY_;

    cudaFuncSetAttribute(k2_rec, cudaFuncAttributeMaxDynamicSharedMemorySize,
                         K2_SMEM_BYTES);

    k0_prep<<<256, 256>>>(Wx, Wu, Wd, Wy);
    k1_fud<<<dim3(TB_/128, 4), 256>>>(U, D, bx, bu, bd, Xout);
    k2_rec<<<B_/8, 512, K2_SMEM_BYTES>>>(x, Xout);
    k3_y<<<TB_/128, 256>>>(Xout, by, Yout);
    k4_fin<<<1, 1>>>(Rout);
}

// round 10
// speedup vs baseline: 1.2266x; 1.2266x over previous
#include <cuda_runtime.h>

#define T_  256
#define B_  1024
#define NX_ 256
#define NY_ 64
#define NU_ 64
#define ND_ 32
#define TB_ (T_*B_)

typedef unsigned long long ull;

// ---- device globals ----
__device__ float  g_WxT [NX_*NX_];   // [k][j]
__device__ float  g_WudT[96*NX_];    // [k][j]
__device__ float  g_WyT [NX_*NY_];   // [k][j]
__device__ double g_acc[6];          // 0:sxmin 1:sxmax 2:sumin 3:sumax 4:sdx 5:dxd

// ---- packed fp32x2 helpers ----
__device__ __forceinline__ ull pk2(float lo, float hi){
    ull r;
    asm("mov.b64 %0, {%1, %2};" : "=l"(r) : "f"(lo), "f"(hi));
    return r;
}
__device__ __forceinline__ void upk2(ull v, float& lo, float& hi){
    asm("mov.b64 {%0, %1}, %2;" : "=f"(lo), "=f"(hi) : "l"(v));
}
__device__ __forceinline__ ull fma2(ull a, ull b, ull c){
    ull d;
    asm("fma.rn.f32x2 %0, %1, %2, %3;" : "=l"(d) : "l"(a), "l"(b), "l"(c));
    return d;
}
__device__ __forceinline__ float warp_sum(float v){
    #pragma unroll
    for (int o = 16; o > 0; o >>= 1) v += __shfl_down_sync(0xffffffffu, v, o);
    return v;
}

// ============================================================================
// K0
// ============================================================================
__global__ void k0_prep(const float* __restrict__ Wx, const float* __restrict__ Wu,
                        const float* __restrict__ Wd, const float* __restrict__ Wy){
    int tid = blockIdx.x * blockDim.x + threadIdx.x;
    int nt  = gridDim.x * blockDim.x;
    if (blockIdx.x == 0 && threadIdx.x < 6) g_acc[threadIdx.x] = 0.0;
    for (int i = tid; i < NX_*NX_; i += nt){ int j = i / NX_, k = i % NX_; g_WxT[k*NX_ + j] = Wx[i]; }
    for (int i = tid; i < NX_*NU_; i += nt){ int j = i / NU_, k = i % NU_; g_WudT[k*NX_ + j] = Wu[i]; }
    for (int i = tid; i < NX_*ND_; i += nt){ int j = i / ND_, k = i % ND_; g_WudT[(64 + k)*NX_ + j] = Wd[i]; }
    for (int i = tid; i < NY_*NX_; i += nt){ int j = i / NX_, k = i % NX_; g_WyT[k*NY_ + j] = Wy[i]; }
}

// ============================================================================
// K1: S = fu + fd + bx. CTA = 128 rows x 64 cols, thread = 8r x 4c.
//     Weights staged in smem (24KB) to remove in-loop LDG latency. [R9 proven]
// ============================================================================
__global__ __launch_bounds__(256, 2) void k1_fud(const float* __restrict__ U,
                                                 const float* __restrict__ D,
                                                 const float* __restrict__ bx,
                                                 const float* __restrict__ bu,
                                                 const float* __restrict__ bd,
                                                 float* __restrict__ Xout){
    __shared__ __align__(16) float uds[96*132];
    __shared__ __align__(16) float ws[96*64];
    __shared__ float red[24];

    const int tid = threadIdx.x;
    const long g0 = (long)blockIdx.x * 128;
    const int cb  = blockIdx.y * 64;

    for (int idx = tid; idx < 96*64; idx += 256){
        int k = idx >> 6, c = idx & 63;
        ws[idx] = g_WudT[k*NX_ + cb + c];
    }
    for (int idx = tid; idx < 128*64; idx += 256){
        int r = idx >> 6, k = idx & 63;
        uds[k*132 + r] = U[(g0 + r)*NU_ + k];
    }
    for (int idx = tid; idx < 128*32; idx += 256){
        int r = idx >> 5, k = idx & 31;
        uds[(64 + k)*132 + r] = D[(g0 + r)*ND_ + k];
    }
    __syncthreads();

    const int r0 = (tid >> 4) * 8;
    const int cl = (tid & 15) * 4;
    const int c0 = cb + cl;

    ull accu[16], accd[16];
    #pragma unroll
    for (int i = 0; i < 16; i++){ accu[i] = 0ull; accd[i] = 0ull; }

    #pragma unroll 4
    for (int k = 0; k < 64; k++){
        float4 w = *(const float4*)&ws[k*64 + cl];
        ull w2[4] = { pk2(w.x, w.x), pk2(w.y, w.y), pk2(w.z, w.z), pk2(w.w, w.w) };
        ulonglong2 qa = *(const ulonglong2*)&uds[k*132 + r0];
        ulonglong2 qb = *(const ulonglong2*)&uds[k*132 + r0 + 4];
        #pragma unroll
        for (int c = 0; c < 4; c++){
            accu[c*4 + 0] = fma2(qa.x, w2[c], accu[c*4 + 0]);
            accu[c*4 + 1] = fma2(qa.y, w2[c], accu[c*4 + 1]);
            accu[c*4 + 2] = fma2(qb.x, w2[c], accu[c*4 + 2]);
            accu[c*4 + 3] = fma2(qb.y, w2[c], accu[c*4 + 3]);
        }
    }
    #pragma unroll 4
    for (int k = 64; k < 96; k++){
        float4 w = *(const float4*)&ws[k*64 + cl];
        ull w2[4] = { pk2(w.x, w.x), pk2(w.y, w.y), pk2(w.z, w.z), pk2(w.w, w.w) };
        ulonglong2 qa = *(const ulonglong2*)&uds[k*132 + r0];
        ulonglong2 qb = *(const ulonglong2*)&uds[k*132 + r0 + 4];
        #pragma unroll
        for (int c = 0; c < 4; c++){
            accd[c*4 + 0] = fma2(qa.x, w2[c], accd[c*4 + 0]);
            accd[c*4 + 1] = fma2(qa.y, w2[c], accd[c*4 + 1]);
            accd[c*4 + 2] = fma2(qb.x, w2[c], accd[c*4 + 2]);
            accd[c*4 + 3] = fma2(qb.y, w2[c], accd[c*4 + 3]);
        }
    }

    float s0 = 0.f, s1 = 0.f, s2 = 0.f;
    float vout[8][4];
    #pragma unroll
    for (int c = 0; c < 4; c++){
        float buc = bu[c0 + c], bdc = bd[c0 + c], bxc = bx[c0 + c];
        #pragma unroll
        for (int p = 0; p < 4; p++){
            float fu0, fu1, fd0, fd1;
            upk2(accu[c*4 + p], fu0, fu1);
            upk2(accd[c*4 + p], fd0, fd1);
            fu0 += buc; fu1 += buc; fd0 += bdc; fd1 += bdc;
            s0 += fmaxf(-fu0 - 1.f, 0.f) + fmaxf(-fu1 - 1.f, 0.f);
            s1 += fmaxf( fu0 - 1.f, 0.f) + fmaxf( fu1 - 1.f, 0.f);
            s2 += fmaxf(-fd0 - 1.f, 0.f) + fmaxf(fd0 - 1.f, 0.f)
                + fmaxf(-fd1 - 1.f, 0.f) + fmaxf(fd1 - 1.f, 0.f);
            vout[2*p    ][c] = fu0 + fd0 + bxc;
            vout[2*p + 1][c] = fu1 + fd1 + bxc;
        }
    }
    #pragma unroll
    for (int rr = 0; rr < 8; rr++){
        float4 o = make_float4(vout[rr][0], vout[rr][1], vout[rr][2], vout[rr][3]);
        *(float4*)&Xout[(g0 + r0 + rr)*NX_ + c0] = o;
    }

    s0 = warp_sum(s0); s1 = warp_sum(s1); s2 = warp_sum(s2);
    int lane = tid & 31, w = tid >> 5;
    if (lane == 0){ red[w] = s0; red[8 + w] = s1; red[16 + w] = s2; }
    __syncthreads();
    if (tid == 0){
        float a = 0, b = 0, c = 0;
        #pragma unroll
        for (int i = 0; i < 8; i++){ a += red[i]; b += red[8 + i]; c += red[16 + i]; }
        atomicAdd(&g_acc[2], (double)a);
        atomicAdd(&g_acc[3], (double)b);
        atomicAdd(&g_acc[5], (double)c);
    }
}

// ============================================================================
// K2: recurrence [REVERTED to R8 best-measured design].
//     128 CTAs x 8 rows, 256 threads = 128 col-pairs x 2 k-halves.
//     192KB (3/4) of WxT in smem; remaining 64 rows streamed with batch-16
//     prefetch covered by 48 smem-fed k-steps. Symmetric epilogue.
// ============================================================================
// floats: wc 2*96*256 = 49152 | xcT 2048 | ps 2*8*256 = 4096 | red 32
#define K2_SMEM_FLOATS (49152 + 2048 + 4096 + 32)
#define K2_SMEM_BYTES  (K2_SMEM_FLOATS * 4)

__global__ __launch_bounds__(256, 1) void k2_rec(const float* __restrict__ x0,
                                                 float* __restrict__ Xout){
    extern __shared__ __align__(16) float sm[];
    float* wc  = sm;                       // [half][kl<96][j<256]
    float* xcT = sm + 49152;               // [k][m]
    float* ps  = sm + 49152 + 2048;        // [half][m][j]
    float* red = sm + 49152 + 2048 + 4096;

    const int tid = threadIdx.x;
    const int kh  = tid >> 7;
    const int c0  = (tid & 127) * 2;
    const long rb = (long)blockIdx.x * 8;

    // cache weight rows kh*128 + [0,96) per half
    for (int idx = tid; idx < 12288; idx += 256){
        int f = idx * 4;
        int h   = f / 24576;
        int rem = f % 24576;
        int kl  = rem >> 8;
        int j   = rem & 255;
        *(float4*)&wc[f] = *(const float4*)&g_WxT[(h*128 + kl)*NX_ + j];
    }
    for (int idx = tid; idx < 8*NX_; idx += 256){
        int m = idx >> 8, k = idx & 255;
        xcT[k*8 + m] = x0[(rb + m)*NX_ + k];
    }
    __syncthreads();

    float sxmin = 0.f, sxmax = 0.f, sdx = 0.f;

    const float* wsbase = wc + (kh*96)*NX_ + c0;             // smem rows kh*128+[0,96)
    const float* wgbase = g_WxT + (kh*128 + 96)*NX_ + c0;    // gmem rows kh*128+[96,128)
    const float* xbase  = xcT + (kh*128)*8;
    float* psme = ps + kh*2048;

    for (int t = 0; t < T_; t++){
        float* Srow = Xout + ((long)t*B_ + rb)*NX_;

        // own-column S values (consumed in epilogue)
        float sv[8];
        #pragma unroll
        for (int m = 0; m < 8; m++) sv[m] = Srow[m*NX_ + tid];

        ull a0[4] = {0,0,0,0}, a1[4] = {0,0,0,0};
        float2 wg[16];

        // P0: prefetch global rows [96,112)
        #pragma unroll
        for (int i = 0; i < 16; i++) wg[i] = *(const float2*)(wgbase + i*NX_);

        // S0: smem k-steps [0,48)
        #pragma unroll 8
        for (int k = 0; k < 48; k++){
            float2 w = *(const float2*)(wsbase + k*NX_);
            const ulonglong2* xr = (const ulonglong2*)(xbase + k*8);
            ulonglong2 q0 = xr[0], q1 = xr[1];
            ull w20 = pk2(w.x, w.x), w21 = pk2(w.y, w.y);
            a0[0] = fma2(q0.x, w20, a0[0]); a0[1] = fma2(q0.y, w20, a0[1]);
            a0[2] = fma2(q1.x, w20, a0[2]); a0[3] = fma2(q1.y, w20, a0[3]);
            a1[0] = fma2(q0.x, w21, a1[0]); a1[1] = fma2(q0.y, w21, a1[1]);
            a1[2] = fma2(q1.x, w21, a1[2]); a1[3] = fma2(q1.y, w21, a1[3]);
        }
        // C0: consume global k [96,112)
        #pragma unroll
        for (int i = 0; i < 16; i++){
            const ulonglong2* xr = (const ulonglong2*)(xbase + (96 + i)*8);
            ulonglong2 q0 = xr[0], q1 = xr[1];
            ull w20 = pk2(wg[i].x, wg[i].x), w21 = pk2(wg[i].y, wg[i].y);
            a0[0] = fma2(q0.x, w20, a0[0]); a0[1] = fma2(q0.y, w20, a0[1]);
            a0[2] = fma2(q1.x, w20, a0[2]); a0[3] = fma2(q1.y, w20, a0[3]);
            a1[0] = fma2(q0.x, w21, a1[0]); a1[1] = fma2(q0.y, w21, a1[1]);
            a1[2] = fma2(q1.x, w21, a1[2]); a1[3] = fma2(q1.y, w21, a1[3]);
        }
        // P1: prefetch global rows [112,128)
        #pragma unroll
        for (int i = 0; i < 16; i++) wg[i] = *(const float2*)(wgbase + (16 + i)*NX_);

        // S1: smem k-steps [48,96)
        #pragma unroll 8
        for (int k = 48; k < 96; k++){
            float2 w = *(const float2*)(wsbase + k*NX_);
            const ulonglong2* xr = (const ulonglong2*)(xbase + k*8);
            ulonglong2 q0 = xr[0], q1 = xr[1];
            ull w20 = pk2(w.x, w.x), w21 = pk2(w.y, w.y);
            a0[0] = fma2(q0.x, w20, a0[0]); a0[1] = fma2(q0.y, w20, a0[1]);
            a0[2] = fma2(q1.x, w20, a0[2]); a0[3] = fma2(q1.y, w20, a0[3]);
            a1[0] = fma2(q0.x, w21, a1[0]); a1[1] = fma2(q0.y, w21, a1[1]);
            a1[2] = fma2(q1.x, w21, a1[2]); a1[3] = fma2(q1.y, w21, a1[3]);
        }
        // C1: consume global k [112,128)
        #pragma unroll
        for (int i = 0; i < 16; i++){
            const ulonglong2* xr = (const ulonglong2*)(xbase + (112 + i)*8);
            ulonglong2 q0 = xr[0], q1 = xr[1];
            ull w20 = pk2(wg[i].x, wg[i].x), w21 = pk2(wg[i].y, wg[i].y);
            a0[0] = fma2(q0.x, w20, a0[0]); a0[1] = fma2(q0.y, w20, a0[1]);
            a0[2] = fma2(q1.x, w20, a0[2]); a0[3] = fma2(q1.y, w20, a0[3]);
            a1[0] = fma2(q0.x, w21, a1[0]); a1[1] = fma2(q0.y, w21, a1[1]);
            a1[2] = fma2(q1.x, w21, a1[2]); a1[3] = fma2(q1.y, w21, a1[3]);
        }

        // both halves dump partials: ps[kh][m][c0..c0+1]
        {
            float f0[8], f1[8];
            #pragma unroll
            for (int p = 0; p < 4; p++){
                upk2(a0[p], f0[2*p], f0[2*p+1]);
                upk2(a1[p], f1[2*p], f1[2*p+1]);
            }
            #pragma unroll
            for (int m = 0; m < 8; m++)
                *(float2*)&psme[m*NX_ + c0] = make_float2(f0[m], f1[m]);
        }
        __syncthreads();

        // symmetric epilogue: thread owns column j = tid, rows 0..7
        {
            float4 xo0 = *(const float4*)&xcT[tid*8];
            float4 xo1 = *(const float4*)&xcT[tid*8 + 4];
            float xold[8] = {xo0.x, xo0.y, xo0.z, xo0.w, xo1.x, xo1.y, xo1.z, xo1.w};
            float xn[8];
            #pragma unroll
            for (int m = 0; m < 8; m++){
                float v = ps[m*NX_ + tid] + ps[2048 + m*NX_ + tid] + sv[m];
                sxmin += fmaxf(-v - 1.f, 0.f);
                sxmax += fmaxf( v - 1.f, 0.f);
                float d = v - xold[m];
                sdx += d*d;
                Srow[m*NX_ + tid] = v;
                xn[m] = v;
            }
            *(float4*)&xcT[tid*8]     = make_float4(xn[0], xn[1], xn[2], xn[3]);
            *(float4*)&xcT[tid*8 + 4] = make_float4(xn[4], xn[5], xn[6], xn[7]);
        }
        __syncthreads();
    }

    sxmin = warp_sum(sxmin); sxmax = warp_sum(sxmax); sdx = warp_sum(sdx);
    int lane = tid & 31, w = tid >> 5;
    if (lane == 0){ red[w] = sxmin; red[8 + w] = sxmax; red[16 + w] = sdx; }
    __syncthreads();
    if (tid == 0){
        float a = 0, b = 0, c = 0;
        #pragma unroll
        for (int i = 0; i < 8; i++){ a += red[i]; b += red[8 + i]; c += red[16 + i]; }
        atomicAdd(&g_acc[0], (double)a);
        atomicAdd(&g_acc[1], (double)b);
        atomicAdd(&g_acc[4], (double)c);
    }
}

// ============================================================================
// K3: Y = X @ Wy^T + by. CTA = 128 rows x 64 cols, thread = 8r x 4c,
//     K staged in 4 chunks of 64; weights ALSO staged in smem. [R9 proven]
// ============================================================================
__global__ __launch_bounds__(256, 4) void k3_y(const float* __restrict__ Xout,
                                               const float* __restrict__ by,
                                               float* __restrict__ Yout){
    __shared__ __align__(16) float xs[64*132];
    __shared__ __align__(16) float ws[64*64];
    const int tid = threadIdx.x;
    const long g0 = (long)blockIdx.x * 128;
    const int r0 = (tid >> 4) * 8;
    const int c0 = (tid & 15) * 4;

    ull acc[16];
    #pragma unroll
    for (int i = 0; i < 16; i++) acc[i] = 0ull;

    for (int ch = 0; ch < 4; ch++){
        if (ch) __syncthreads();
        for (int idx = tid; idx < 128*64; idx += 256){
            int r = idx >> 6, k = idx & 63;
            xs[k*132 + r] = Xout[(g0 + r)*NX_ + ch*64 + k];
        }
        for (int idx = tid; idx < 64*64; idx += 256){
            int k = idx >> 6, c = idx & 63;
            ws[idx] = g_WyT[(ch*64 + k)*NY_ + c];
        }
        __syncthreads();

        #pragma unroll 4
        for (int k = 0; k < 64; k++){
            float4 w = *(const float4*)&ws[k*64 + c0];
            ull w2[4] = { pk2(w.x, w.x), pk2(w.y, w.y), pk2(w.z, w.z), pk2(w.w, w.w) };
            ulonglong2 qa = *(const ulonglong2*)&xs[k*132 + r0];
            ulonglong2 qb = *(const ulonglong2*)&xs[k*132 + r0 + 4];
            #pragma unroll
            for (int c = 0; c < 4; c++){
                acc[c*4 + 0] = fma2(qa.x, w2[c], acc[c*4 + 0]);
                acc[c*4 + 1] = fma2(qa.y, w2[c], acc[c*4 + 1]);
                acc[c*4 + 2] = fma2(qb.x, w2[c], acc[c*4 + 2]);
                acc[c*4 + 3] = fma2(qb.y, w2[c], acc[c*4 + 3]);
            }
        }
    }

    float byv[4] = { by[c0], by[c0+1], by[c0+2], by[c0+3] };
    float vout[8][4];
    #pragma unroll
    for (int c = 0; c < 4; c++){
        #pragma unroll
        for (int p = 0; p < 4; p++){
            float lo, hi;
            upk2(acc[c*4 + p], lo, hi);
            vout[2*p    ][c] = lo + byv[c];
            vout[2*p + 1][c] = hi + byv[c];
        }
    }
    #pragma unroll
    for (int rr = 0; rr < 8; rr++){
        float4 o = make_float4(vout[rr][0], vout[rr][1], vout[rr][2], vout[rr][3]);
        *(float4*)&Yout[(g0 + r0 + rr)*NY_ + c0] = o;
    }
}

// ============================================================================
// K4
// ============================================================================
__global__ void k4_fin(float* __restrict__ out_reg){
    double inv = 1.0 / ((double)T_ * (double)B_ * (double)NX_);
    double s = g_acc[0] + g_acc[1] + 2.0*(g_acc[2] + g_acc[3]) + g_acc[4] + g_acc[5];
    *out_reg = (float)(0.2 * s * inv);
}

extern "C" void kernel_launch(void* const* d_in, const int* in_sizes, int n_in,
                              void* d_out, int out_size){
    const float* x  = (const float*)d_in[0];
    const float* U  = (const float*)d_in[1];
    const float* D  = (const float*)d_in[2];
    const float* Wx = (const float*)d_in[3];
    const float* bx = (const float*)d_in[4];
    const float* Wu = (const float*)d_in[5];
    const float* bu = (const float*)d_in[6];
    const float* Wd = (const float*)d_in[7];
    const float* bd = (const float*)d_in[8];
    const float* Wy = (const float*)d_in[9];
    const float* by = (const float*)d_in[10];

    float* out  = (float*)d_out;
    float* Xout = out;
    float* Yout = out + (size_t)TB_ * NX_;
    float* Rout = out + (size_t)TB_ * NX_ + (size_t)TB_ * NY_;

    cudaFuncSetAttribute(k2_rec, cudaFuncAttributeMaxDynamicSharedMemorySize,
                         K2_SMEM_BYTES);

    k0_prep<<<256, 256>>>(Wx, Wu, Wd, Wy);
    k1_fud<<<dim3(TB_/128, 4), 256>>>(U, D, bx, bu, bd, Xout);
    k2_rec<<<B_/8, 256, K2_SMEM_BYTES>>>(x, Xout);
    k3_y<<<TB_/128, 256>>>(Xout, by, Yout);
    k4_fin<<<1, 1>>>(Rout);
}